// round 13
// baseline (speedup 1.0000x reference)
#include <cuda_runtime.h>
#include <math.h>

#define BATCH 32
#define HH 76
#define WW 76
#define AA 3
#define NCLS 80
#define SPAT (HH*WW)          /* 5776 */
#define NCAND (SPAT*AA)       /* 17328 */
#define MAXDET 300
#define NWORDS 10             /* ceil(300/32) */
#define X_ELEMS (BATCH * (AA*(5+NCLS)) * SPAT)   /* 47,174,400 */

// ---------------- scratch (no allocation allowed) ----------------
// Referenced ONLY from device code.
__device__ float         g_masked[BATCH*NCAND];
__device__ unsigned char g_label [BATCH*NCAND];
__device__ int           g_selidx[BATCH*MAXDET];
__device__ float         g_selmask[BATCH*MAXDET];

// ---------- XLA LogisticExpander: logistic(x) = 1/(1+exp(-x)) ----------
// XLA GPU emits f32 exp as libdevice __nv_expf == CUDA expf (no fast-math).
__device__ __forceinline__ float xla_sigmoid(float x) {
    return __fdiv_rn(1.0f, __fadd_rn(1.0f, expf(-x)));
}

// monotonic float -> uint mapping (order-preserving)
__device__ __forceinline__ unsigned ordf(float f) {
    unsigned u = __float_as_uint(f);
    return (u & 0x80000000u) ? ~u : (u | 0x80000000u);
}

// ================= K1: streaming decode of scores/labels =================
// thread = one (spatial, anchor) candidate; loads coalesced across s.
__global__ void k_decode(const float* __restrict__ x) {
    int s = blockIdx.x * blockDim.x + threadIdx.x;
    int a = blockIdx.y;
    int b = blockIdx.z;
    if (s >= SPAT) return;
    const float* p = x + ((size_t)b * (AA * 85) + (size_t)a * 85) * SPAT + s;

    float v[NCLS];
    #pragma unroll
    for (int f = 0; f < NCLS; ++f)
        v[f] = __ldg(p + (size_t)(5 + f) * SPAT);
    float tobj = __ldg(p + 4 * SPAT);

    float mv = v[0];
    #pragma unroll
    for (int f = 1; f < NCLS; ++f) mv = fmaxf(mv, v[f]);

    // Exact max(sigmoid(cls)) + first-index argmax without 80 expf calls:
    // rounded sigmoid is monotone except within ~1ulp windows, so only logits
    // within 0.004 of mv can attain the post-rounding max.
    float win = __fadd_rn(mv, -0.004f);
    float smax = -1.0f; int lab = 0;
    #pragma unroll
    for (int f = 0; f < NCLS; ++f) {
        if (v[f] >= win) {
            float sv = xla_sigmoid(v[f]);
            if (sv > smax) { smax = sv; lab = f; }   // strict >: first index wins
        }
    }

    float obj_s = xla_sigmoid(tobj);
    float score = __fmul_rn(smax, obj_s);
    bool valid = (obj_s >= 0.5f) && (score >= 0.05f);

    int n = s * AA + a;   // reference flatten order [H,W,A]
    g_masked[(size_t)b * NCAND + n] = valid ? score : -1.0f;
    g_label [(size_t)b * NCAND + n] = (unsigned char)lab;
}

// ================= K2: exact top-300 per batch =================
// 4x8-bit radix select (warp-aggregated histogram atomics), exact
// lowest-index tie handling, then 512-wide bitonic sort of
// (ord<<32 | ~idx) keys descending.
__global__ __launch_bounds__(1024) void k_select() {
    const int bdim = 1024;
    int b = blockIdx.x, tid = threadIdx.x;
    int lane = tid & 31;
    const float* ms = g_masked + (size_t)b * NCAND;

    __shared__ unsigned hist[256];
    __shared__ unsigned long long keys[512];
    __shared__ int sh_chosen, sh_k, sh_cnt, sh_running;
    __shared__ int wsum[32], woff[33];

    unsigned prefix = 0, pmask = 0;
    int k = MAXDET;
    for (int pass = 0; pass < 4; ++pass) {
        int shift = 24 - 8 * pass;
        for (int i = tid; i < 256; i += bdim) hist[i] = 0;
        __syncthreads();
        for (int base = 0; base < NCAND; base += bdim) {
            int i = base + tid;
            unsigned key = 0x100u;            // sentinel: no contribution
            if (i < NCAND) {
                unsigned u = ordf(ms[i]);
                if ((u & pmask) == prefix) key = (u >> shift) & 255;
            }
            unsigned grp = __match_any_sync(0xFFFFFFFFu, key);
            int leader = __ffs((int)grp) - 1;
            if (key != 0x100u && lane == leader)
                atomicAdd(&hist[key], (unsigned)__popc(grp));
        }
        __syncthreads();
        if (tid == 0) {
            int cum = 0, chosen = 0, kk = k;
            for (int bin = 255; bin >= 0; --bin) {
                int c = (int)hist[bin];
                if (cum + c >= kk) { chosen = bin; kk -= cum; break; }
                cum += c;
            }
            sh_chosen = chosen; sh_k = kk;
        }
        __syncthreads();
        prefix |= ((unsigned)sh_chosen << shift);
        pmask  |= (0xFFu << shift);
        k = sh_k;
        __syncthreads();
    }
    unsigned T = prefix;        // 300th value's ordered bits
    int need = k;               // taken from the ==T tier (lowest indices)

    if (tid == 0) { sh_cnt = 0; sh_running = 0; }
    for (int i = tid; i < 512; i += bdim) keys[i] = 0ull;
    __syncthreads();

    // strictly-greater elements (count = 300 - need); order fixed by sort
    for (int i = tid; i < NCAND; i += bdim) {
        unsigned u = ordf(ms[i]);
        if (u > T) {
            int p = atomicAdd(&sh_cnt, 1);
            if (p < 512)
                keys[p] = ((unsigned long long)u << 32) |
                          (unsigned long long)(0xFFFFFFFFu - (unsigned)i);
        }
    }
    __syncthreads();
    int cntGt = sh_cnt;

    // ==T ties in ascending global index order (exact top_k tie semantics)
    int wrp = tid >> 5;
    for (int base = 0; base < NCAND; base += bdim) {
        int i = base + tid;
        int flag = (i < NCAND) && (ordf(ms[i]) == T);
        unsigned bal = __ballot_sync(0xFFFFFFFFu, flag);
        if (lane == 0) wsum[wrp] = __popc(bal);
        __syncthreads();
        if (tid == 0) {
            int acc = 0;
            for (int w2 = 0; w2 < 32; ++w2) { woff[w2] = acc; acc += wsum[w2]; }
            woff[32] = acc;
        }
        __syncthreads();
        if (flag) {
            int rank = __popc(bal & ((1u << lane) - 1u));
            int pos = sh_running + woff[wrp] + rank;
            int dst = cntGt + pos;
            if (pos < need && dst < 512)
                keys[dst] = ((unsigned long long)T << 32) |
                            (unsigned long long)(0xFFFFFFFFu - (unsigned)i);
        }
        __syncthreads();
        if (tid == 0) sh_running += woff[32];
        __syncthreads();
    }

    // bitonic sort 512 keys, descending (zero pad sorts last)
    for (int kk = 2; kk <= 512; kk <<= 1) {
        for (int j = kk >> 1; j > 0; j >>= 1) {
            if (tid < 512) {
                int ixj = tid ^ j;
                if (ixj > tid) {
                    unsigned long long va = keys[tid], vc = keys[ixj];
                    bool desc = ((tid & kk) == 0);
                    if (desc ? (va < vc) : (va > vc)) { keys[tid] = vc; keys[ixj] = va; }
                }
            }
            __syncthreads();
        }
    }

    for (int j = tid; j < MAXDET; j += bdim) {
        unsigned long long key = keys[j];
        int idx = (int)(0xFFFFFFFFu - (unsigned)(key & 0xFFFFFFFFull));
        if (idx < 0 || idx >= NCAND) idx = 0;
        g_selidx [b * MAXDET + j] = idx;
        g_selmask[b * MAXDET + j] = ms[idx];
    }
}

// ======== K3: fused box decode + parallel-bitmask NMS (block per batch) ====
__global__ __launch_bounds__(1024) void k_boxnms(const float* __restrict__ x,
                                                 const float* __restrict__ anchors,
                                                 float* __restrict__ out) {
    __shared__ float4   bx[MAXDET];
    __shared__ unsigned sup[MAXDET * NWORDS];
    __shared__ unsigned keepw_s[NWORDS];
    int b = blockIdx.x, tid = threadIdx.x;

    // ---- Phase A: decode selected boxes; write boxes/scores/labels ----
    if (tid < MAXDET) {
        int t = b * MAXDET + tid;
        int idx = g_selidx[t];
        float m = g_selmask[t];
        int a = idx % AA;
        int s = idx / AA;
        int hh = s / WW, ww = s % WW;

        const float* p = x + ((size_t)b * (AA * 85) + (size_t)a * 85) * SPAT + s;
        float t0 = __ldg(p), t1 = __ldg(p + SPAT);
        float t2 = __ldg(p + 2 * SPAT), t3 = __ldg(p + 3 * SPAT);

        float sx = __fsub_rn(__fmul_rn(1.2f, xla_sigmoid(t0)), 0.1f);
        float sy = __fsub_rn(__fmul_rn(1.2f, xla_sigmoid(t1)), 0.1f);
        float bxc = __fdiv_rn(__fadd_rn(sx, (float)ww), (float)WW);
        float byc = __fdiv_rn(__fadd_rn(sy, (float)hh), (float)HH);
        float bw = fminf(fmaxf(__fmul_rn(expf(t2), __ldg(anchors + a * 2 + 0)), 0.0f), 2.0f);
        float bh = fminf(fmaxf(__fmul_rn(expf(t3), __ldg(anchors + a * 2 + 1)), 0.0f), 2.0f);
        float x1 = __fsub_rn(bxc, __fmul_rn(0.5f, bw));
        float y1 = __fsub_rn(byc, __fmul_rn(0.5f, bh));
        float x2 = __fadd_rn(x1, bw);
        float y2 = __fadd_rn(y1, bh);
        x1 = fminf(fmaxf(x1, 0.0f), 1.0f);
        y1 = fminf(fmaxf(y1, 0.0f), 1.0f);
        x2 = fminf(fmaxf(x2, 0.0f), 1.0f);
        y2 = fminf(fmaxf(y2, 0.0f), 1.0f);

        bx[tid] = make_float4(x1, y1, x2, y2);
        float* ob = out + (size_t)t * 4;
        ob[0] = x1; ob[1] = y1; ob[2] = x2; ob[3] = y2;
        out[(size_t)BATCH * MAXDET * 4 + t] = (m >= 0.0f) ? m : 0.0f;
        out[(size_t)BATCH * MAXDET * 5 + t] = (float)g_label[(size_t)b * NCAND + idx];
    }
    __syncthreads();

    // ---- Phase B: suppression bit matrix (iou > 0.7, j > i) in parallel ----
    for (int task = tid; task < MAXDET * NWORDS; task += blockDim.x) {
        int i = task / NWORDS, w = task % NWORDS;
        float4 bi = bx[i];
        float ai = __fmul_rn(__fsub_rn(bi.z, bi.x), __fsub_rn(bi.w, bi.y));
        unsigned bits = 0;
        int j0 = w * 32;
        #pragma unroll 8
        for (int jj = 0; jj < 32; ++jj) {
            int j = j0 + jj;
            if (j > i && j < MAXDET) {
                float4 bj = bx[j];
                float lx = fmaxf(bi.x, bj.x), ly = fmaxf(bi.y, bj.y);
                float rx = fminf(bi.z, bj.z), ry = fminf(bi.w, bj.w);
                float iw = fmaxf(__fsub_rn(rx, lx), 0.0f);
                float ih = fmaxf(__fsub_rn(ry, ly), 0.0f);
                float inter = __fmul_rn(iw, ih);
                float aj = __fmul_rn(__fsub_rn(bj.z, bj.x), __fsub_rn(bj.w, bj.y));
                float den = __fadd_rn(__fsub_rn(__fadd_rn(ai, aj), inter), 1e-9f);
                float iou = __fdiv_rn(inter, den);
                if (iou > 0.7f) bits |= (1u << jj);
            }
        }
        sup[task] = bits;
    }
    __syncthreads();

    // ---- Phase C: sequential greedy scan on one warp (bit ops only) ----
    if (tid < 32) {
        int l = tid;
        unsigned kw = 0;
        if (l < NWORDS) {
            for (int jj = 0; jj < 32; ++jj) {
                int j = l * 32 + jj;
                if (j < MAXDET && g_selmask[b * MAXDET + j] >= 0.0f) kw |= (1u << jj);
            }
        }
        for (int i = 0; i < MAXDET; ++i) {
            unsigned wrd = __shfl_sync(0xFFFFFFFFu, kw, i >> 5);
            if ((wrd >> (i & 31)) & 1u) {            // warp-uniform branch
                if (l < NWORDS) kw &= ~sup[i * NWORDS + l];
            }
        }
        if (l < NWORDS) keepw_s[l] = kw;
    }
    __syncthreads();
    for (int j = tid; j < MAXDET; j += blockDim.x)
        out[(size_t)BATCH * MAXDET * 6 + b * MAXDET + j] =
            ((keepw_s[j >> 5] >> (j & 31)) & 1u) ? 1.0f : 0.0f;
}

// ================= launch =================
extern "C" void kernel_launch(void* const* d_in, const int* in_sizes, int n_in,
                              void* d_out, int out_size) {
    (void)out_size;
    const float* x       = (const float*)d_in[0];
    const float* anchors = (const float*)d_in[1];
    if (n_in >= 2) {
        if (in_sizes[1] == X_ELEMS || in_sizes[0] < in_sizes[1]) {
            x = (const float*)d_in[1]; anchors = (const float*)d_in[0];
        }
    }
    float* out = (float*)d_out;

    dim3 g1((SPAT + 127) / 128, AA, BATCH);
    k_decode<<<g1, 128>>>(x);
    k_select<<<BATCH, 1024>>>();
    k_boxnms<<<BATCH, 1024>>>(x, anchors, out);
}

// round 14
// speedup vs baseline: 1.0017x; 1.0017x over previous
#include <cuda_runtime.h>
#include <math.h>

#define BATCH 32
#define HH 76
#define WW 76
#define AA 3
#define NCLS 80
#define SPAT (HH*WW)          /* 5776 */
#define NCAND (SPAT*AA)       /* 17328 */
#define MAXDET 300
#define NWORDS 10             /* ceil(300/32) */
#define X_ELEMS (BATCH * (AA*(5+NCLS)) * SPAT)   /* 47,174,400 */

// ---------------- scratch (no allocation allowed) ----------------
// Referenced ONLY from device code.
__device__ float         g_masked[BATCH*NCAND];
__device__ unsigned char g_label [BATCH*NCAND];
__device__ int           g_selidx[BATCH*MAXDET];
__device__ float         g_selmask[BATCH*MAXDET];

// ---------- XLA LogisticExpander: logistic(x) = 1/(1+exp(-x)) ----------
// XLA GPU emits f32 exp as libdevice __nv_expf == CUDA expf (no fast-math).
__device__ __forceinline__ float xla_sigmoid(float x) {
    return __fdiv_rn(1.0f, __fadd_rn(1.0f, expf(-x)));
}

// monotonic float -> uint mapping (order-preserving)
__device__ __forceinline__ unsigned ordf(float f) {
    unsigned u = __float_as_uint(f);
    return (u & 0x80000000u) ? ~u : (u | 0x80000000u);
}

// ================= K1: streaming decode of scores/labels =================
// thread = one (spatial, anchor) candidate; loads coalesced across s.
__global__ void k_decode(const float* __restrict__ x) {
    int s = blockIdx.x * blockDim.x + threadIdx.x;
    int a = blockIdx.y;
    int b = blockIdx.z;
    if (s >= SPAT) return;
    const float* p = x + ((size_t)b * (AA * 85) + (size_t)a * 85) * SPAT + s;

    float v[NCLS];
    #pragma unroll
    for (int f = 0; f < NCLS; ++f)
        v[f] = __ldg(p + (size_t)(5 + f) * SPAT);
    float tobj = __ldg(p + 4 * SPAT);

    float mv = v[0];
    #pragma unroll
    for (int f = 1; f < NCLS; ++f) mv = fmaxf(mv, v[f]);

    // Exact max(sigmoid(cls)) + first-index argmax without 80 expf calls:
    // rounded sigmoid is monotone except within ~1ulp windows, so only logits
    // within 0.004 of mv can attain the post-rounding max.
    float win = __fadd_rn(mv, -0.004f);
    float smax = -1.0f; int lab = 0;
    #pragma unroll
    for (int f = 0; f < NCLS; ++f) {
        if (v[f] >= win) {
            float sv = xla_sigmoid(v[f]);
            if (sv > smax) { smax = sv; lab = f; }   // strict >: first index wins
        }
    }

    float obj_s = xla_sigmoid(tobj);
    float score = __fmul_rn(smax, obj_s);
    bool valid = (obj_s >= 0.5f) && (score >= 0.05f);

    int n = s * AA + a;   // reference flatten order [H,W,A]
    g_masked[(size_t)b * NCAND + n] = valid ? score : -1.0f;
    g_label [(size_t)b * NCAND + n] = (unsigned char)lab;
}

// ================= K2: exact top-300 per batch =================
// 4x8-bit radix select (warp-aggregated histogram atomics), exact
// lowest-index tie handling, then 512-wide bitonic sort of
// (ord<<32 | ~idx) keys descending.
__global__ __launch_bounds__(1024) void k_select() {
    const int bdim = 1024;
    int b = blockIdx.x, tid = threadIdx.x;
    int lane = tid & 31;
    const float* ms = g_masked + (size_t)b * NCAND;

    __shared__ unsigned hist[256];
    __shared__ unsigned long long keys[512];
    __shared__ int sh_chosen, sh_k, sh_cnt, sh_running;
    __shared__ int wsum[32], woff[33];

    unsigned prefix = 0, pmask = 0;
    int k = MAXDET;
    for (int pass = 0; pass < 4; ++pass) {
        int shift = 24 - 8 * pass;
        for (int i = tid; i < 256; i += bdim) hist[i] = 0;
        __syncthreads();
        for (int base = 0; base < NCAND; base += bdim) {
            int i = base + tid;
            unsigned key = 0x100u;            // sentinel: no contribution
            if (i < NCAND) {
                unsigned u = ordf(ms[i]);
                if ((u & pmask) == prefix) key = (u >> shift) & 255;
            }
            unsigned grp = __match_any_sync(0xFFFFFFFFu, key);
            int leader = __ffs((int)grp) - 1;
            if (key != 0x100u && lane == leader)
                atomicAdd(&hist[key], (unsigned)__popc(grp));
        }
        __syncthreads();
        if (tid == 0) {
            int cum = 0, chosen = 0, kk = k;
            for (int bin = 255; bin >= 0; --bin) {
                int c = (int)hist[bin];
                if (cum + c >= kk) { chosen = bin; kk -= cum; break; }
                cum += c;
            }
            sh_chosen = chosen; sh_k = kk;
        }
        __syncthreads();
        prefix |= ((unsigned)sh_chosen << shift);
        pmask  |= (0xFFu << shift);
        k = sh_k;
        __syncthreads();
    }
    unsigned T = prefix;        // 300th value's ordered bits
    int need = k;               // taken from the ==T tier (lowest indices)

    if (tid == 0) { sh_cnt = 0; sh_running = 0; }
    for (int i = tid; i < 512; i += bdim) keys[i] = 0ull;
    __syncthreads();

    // strictly-greater elements (count = 300 - need); order fixed by sort
    for (int i = tid; i < NCAND; i += bdim) {
        unsigned u = ordf(ms[i]);
        if (u > T) {
            int p = atomicAdd(&sh_cnt, 1);
            if (p < 512)
                keys[p] = ((unsigned long long)u << 32) |
                          (unsigned long long)(0xFFFFFFFFu - (unsigned)i);
        }
    }
    __syncthreads();
    int cntGt = sh_cnt;

    // ==T ties in ascending global index order (exact top_k tie semantics)
    int wrp = tid >> 5;
    for (int base = 0; base < NCAND; base += bdim) {
        int i = base + tid;
        int flag = (i < NCAND) && (ordf(ms[i]) == T);
        unsigned bal = __ballot_sync(0xFFFFFFFFu, flag);
        if (lane == 0) wsum[wrp] = __popc(bal);
        __syncthreads();
        if (tid == 0) {
            int acc = 0;
            for (int w2 = 0; w2 < 32; ++w2) { woff[w2] = acc; acc += wsum[w2]; }
            woff[32] = acc;
        }
        __syncthreads();
        if (flag) {
            int rank = __popc(bal & ((1u << lane) - 1u));
            int pos = sh_running + woff[wrp] + rank;
            int dst = cntGt + pos;
            if (pos < need && dst < 512)
                keys[dst] = ((unsigned long long)T << 32) |
                            (unsigned long long)(0xFFFFFFFFu - (unsigned)i);
        }
        __syncthreads();
        if (tid == 0) sh_running += woff[32];
        __syncthreads();
    }

    // bitonic sort 512 keys, descending (zero pad sorts last)
    for (int kk = 2; kk <= 512; kk <<= 1) {
        for (int j = kk >> 1; j > 0; j >>= 1) {
            if (tid < 512) {
                int ixj = tid ^ j;
                if (ixj > tid) {
                    unsigned long long va = keys[tid], vc = keys[ixj];
                    bool desc = ((tid & kk) == 0);
                    if (desc ? (va < vc) : (va > vc)) { keys[tid] = vc; keys[ixj] = va; }
                }
            }
            __syncthreads();
        }
    }

    for (int j = tid; j < MAXDET; j += bdim) {
        unsigned long long key = keys[j];
        int idx = (int)(0xFFFFFFFFu - (unsigned)(key & 0xFFFFFFFFull));
        if (idx < 0 || idx >= NCAND) idx = 0;
        g_selidx [b * MAXDET + j] = idx;
        g_selmask[b * MAXDET + j] = ms[idx];
    }
}

// ======== K3: fused box decode + parallel-bitmask NMS (block per batch) ====
__global__ __launch_bounds__(1024) void k_boxnms(const float* __restrict__ x,
                                                 const float* __restrict__ anchors,
                                                 float* __restrict__ out) {
    __shared__ float4   bx[MAXDET];
    __shared__ unsigned sup[MAXDET * NWORDS];
    __shared__ unsigned keepw_s[NWORDS];
    int b = blockIdx.x, tid = threadIdx.x;

    // ---- Phase A: decode selected boxes; write boxes/scores/labels ----
    if (tid < MAXDET) {
        int t = b * MAXDET + tid;
        int idx = g_selidx[t];
        float m = g_selmask[t];
        int a = idx % AA;
        int s = idx / AA;
        int hh = s / WW, ww = s % WW;

        const float* p = x + ((size_t)b * (AA * 85) + (size_t)a * 85) * SPAT + s;
        float t0 = __ldg(p), t1 = __ldg(p + SPAT);
        float t2 = __ldg(p + 2 * SPAT), t3 = __ldg(p + 3 * SPAT);

        float sx = __fsub_rn(__fmul_rn(1.2f, xla_sigmoid(t0)), 0.1f);
        float sy = __fsub_rn(__fmul_rn(1.2f, xla_sigmoid(t1)), 0.1f);
        float bxc = __fdiv_rn(__fadd_rn(sx, (float)ww), (float)WW);
        float byc = __fdiv_rn(__fadd_rn(sy, (float)hh), (float)HH);
        float bw = fminf(fmaxf(__fmul_rn(expf(t2), __ldg(anchors + a * 2 + 0)), 0.0f), 2.0f);
        float bh = fminf(fmaxf(__fmul_rn(expf(t3), __ldg(anchors + a * 2 + 1)), 0.0f), 2.0f);
        float x1 = __fsub_rn(bxc, __fmul_rn(0.5f, bw));
        float y1 = __fsub_rn(byc, __fmul_rn(0.5f, bh));
        float x2 = __fadd_rn(x1, bw);
        float y2 = __fadd_rn(y1, bh);
        x1 = fminf(fmaxf(x1, 0.0f), 1.0f);
        y1 = fminf(fmaxf(y1, 0.0f), 1.0f);
        x2 = fminf(fmaxf(x2, 0.0f), 1.0f);
        y2 = fminf(fmaxf(y2, 0.0f), 1.0f);

        bx[tid] = make_float4(x1, y1, x2, y2);
        float* ob = out + (size_t)t * 4;
        ob[0] = x1; ob[1] = y1; ob[2] = x2; ob[3] = y2;
        out[(size_t)BATCH * MAXDET * 4 + t] = (m >= 0.0f) ? m : 0.0f;
        out[(size_t)BATCH * MAXDET * 5 + t] = (float)g_label[(size_t)b * NCAND + idx];
    }
    __syncthreads();

    // ---- Phase B: suppression bit matrix (iou > 0.7, j > i) in parallel ----
    for (int task = tid; task < MAXDET * NWORDS; task += blockDim.x) {
        int i = task / NWORDS, w = task % NWORDS;
        float4 bi = bx[i];
        float ai = __fmul_rn(__fsub_rn(bi.z, bi.x), __fsub_rn(bi.w, bi.y));
        unsigned bits = 0;
        int j0 = w * 32;
        #pragma unroll 8
        for (int jj = 0; jj < 32; ++jj) {
            int j = j0 + jj;
            if (j > i && j < MAXDET) {
                float4 bj = bx[j];
                float lx = fmaxf(bi.x, bj.x), ly = fmaxf(bi.y, bj.y);
                float rx = fminf(bi.z, bj.z), ry = fminf(bi.w, bj.w);
                float iw = fmaxf(__fsub_rn(rx, lx), 0.0f);
                float ih = fmaxf(__fsub_rn(ry, ly), 0.0f);
                float inter = __fmul_rn(iw, ih);
                float aj = __fmul_rn(__fsub_rn(bj.z, bj.x), __fsub_rn(bj.w, bj.y));
                float den = __fadd_rn(__fsub_rn(__fadd_rn(ai, aj), inter), 1e-9f);
                float iou = __fdiv_rn(inter, den);
                if (iou > 0.7f) bits |= (1u << jj);
            }
        }
        sup[task] = bits;
    }
    __syncthreads();

    // ---- Phase C: sequential greedy scan on one warp (bit ops only) ----
    if (tid < 32) {
        int l = tid;
        unsigned kw = 0;
        if (l < NWORDS) {
            for (int jj = 0; jj < 32; ++jj) {
                int j = l * 32 + jj;
                if (j < MAXDET && g_selmask[b * MAXDET + j] >= 0.0f) kw |= (1u << jj);
            }
        }
        for (int i = 0; i < MAXDET; ++i) {
            unsigned wrd = __shfl_sync(0xFFFFFFFFu, kw, i >> 5);
            if ((wrd >> (i & 31)) & 1u) {            // warp-uniform branch
                if (l < NWORDS) kw &= ~sup[i * NWORDS + l];
            }
        }
        if (l < NWORDS) keepw_s[l] = kw;
    }
    __syncthreads();
    for (int j = tid; j < MAXDET; j += blockDim.x)
        out[(size_t)BATCH * MAXDET * 6 + b * MAXDET + j] =
            ((keepw_s[j >> 5] >> (j & 31)) & 1u) ? 1.0f : 0.0f;
}

// ================= launch =================
extern "C" void kernel_launch(void* const* d_in, const int* in_sizes, int n_in,
                              void* d_out, int out_size) {
    (void)out_size;
    const float* x       = (const float*)d_in[0];
    const float* anchors = (const float*)d_in[1];
    if (n_in >= 2) {
        if (in_sizes[1] == X_ELEMS || in_sizes[0] < in_sizes[1]) {
            x = (const float*)d_in[1]; anchors = (const float*)d_in[0];
        }
    }
    float* out = (float*)d_out;

    dim3 g1((SPAT + 127) / 128, AA, BATCH);
    k_decode<<<g1, 128>>>(x);
    k_select<<<BATCH, 1024>>>();
    k_boxnms<<<BATCH, 1024>>>(x, anchors, out);
}

// round 15
// speedup vs baseline: 1.0095x; 1.0078x over previous
#include <cuda_runtime.h>
#include <math.h>

#define BATCH 32
#define HH 76
#define WW 76
#define AA 3
#define NCLS 80
#define SPAT (HH*WW)          /* 5776 */
#define NCAND (SPAT*AA)       /* 17328 */
#define MAXDET 300
#define NWORDS 10             /* ceil(300/32) */
#define X_ELEMS (BATCH * (AA*(5+NCLS)) * SPAT)   /* 47,174,400 */

// ---------------- scratch (no allocation allowed) ----------------
// Referenced ONLY from device code.
__device__ float         g_masked[BATCH*NCAND];
__device__ unsigned char g_label [BATCH*NCAND];
__device__ int           g_selidx[BATCH*MAXDET];
__device__ float         g_selmask[BATCH*MAXDET];

// ---------- XLA LogisticExpander: logistic(x) = 1/(1+exp(-x)) ----------
// XLA GPU emits f32 exp as libdevice __nv_expf == CUDA expf (no fast-math).
__device__ __forceinline__ float xla_sigmoid(float x) {
    return __fdiv_rn(1.0f, __fadd_rn(1.0f, expf(-x)));
}

// monotonic float -> uint mapping (order-preserving)
__device__ __forceinline__ unsigned ordf(float f) {
    unsigned u = __float_as_uint(f);
    return (u & 0x80000000u) ? ~u : (u | 0x80000000u);
}

// ================= K1: streaming decode of scores/labels =================
// thread = one (spatial, anchor) candidate; loads coalesced across s.
__global__ void k_decode(const float* __restrict__ x) {
    int s = blockIdx.x * blockDim.x + threadIdx.x;
    int a = blockIdx.y;
    int b = blockIdx.z;
    if (s >= SPAT) return;
    const float* p = x + ((size_t)b * (AA * 85) + (size_t)a * 85) * SPAT + s;

    float v[NCLS];
    #pragma unroll
    for (int f = 0; f < NCLS; ++f)
        v[f] = __ldg(p + (size_t)(5 + f) * SPAT);
    float tobj = __ldg(p + 4 * SPAT);

    float mv = v[0];
    #pragma unroll
    for (int f = 1; f < NCLS; ++f) mv = fmaxf(mv, v[f]);

    // Exact max(sigmoid(cls)) + first-index argmax without 80 expf calls:
    // rounded sigmoid is monotone except within ~1ulp windows, so only logits
    // within 0.004 of mv can attain the post-rounding max.
    float win = __fadd_rn(mv, -0.004f);
    float smax = -1.0f; int lab = 0;
    #pragma unroll
    for (int f = 0; f < NCLS; ++f) {
        if (v[f] >= win) {
            float sv = xla_sigmoid(v[f]);
            if (sv > smax) { smax = sv; lab = f; }   // strict >: first index wins
        }
    }

    float obj_s = xla_sigmoid(tobj);
    float score = __fmul_rn(smax, obj_s);
    bool valid = (obj_s >= 0.5f) && (score >= 0.05f);

    int n = s * AA + a;   // reference flatten order [H,W,A]
    g_masked[(size_t)b * NCAND + n] = valid ? score : -1.0f;
    g_label [(size_t)b * NCAND + n] = (unsigned char)lab;
}

// ================= K2: exact top-300 per batch =================
// 4x8-bit radix select (warp-aggregated histogram atomics), exact
// lowest-index tie handling, then 512-wide bitonic sort of
// (ord<<32 | ~idx) keys descending.
__global__ __launch_bounds__(1024) void k_select() {
    const int bdim = 1024;
    int b = blockIdx.x, tid = threadIdx.x;
    int lane = tid & 31;
    const float* ms = g_masked + (size_t)b * NCAND;

    __shared__ unsigned hist[256];
    __shared__ unsigned long long keys[512];
    __shared__ int sh_chosen, sh_k, sh_cnt, sh_running;
    __shared__ int wsum[32], woff[33];

    unsigned prefix = 0, pmask = 0;
    int k = MAXDET;
    for (int pass = 0; pass < 4; ++pass) {
        int shift = 24 - 8 * pass;
        for (int i = tid; i < 256; i += bdim) hist[i] = 0;
        __syncthreads();
        for (int base = 0; base < NCAND; base += bdim) {
            int i = base + tid;
            unsigned key = 0x100u;            // sentinel: no contribution
            if (i < NCAND) {
                unsigned u = ordf(ms[i]);
                if ((u & pmask) == prefix) key = (u >> shift) & 255;
            }
            unsigned grp = __match_any_sync(0xFFFFFFFFu, key);
            int leader = __ffs((int)grp) - 1;
            if (key != 0x100u && lane == leader)
                atomicAdd(&hist[key], (unsigned)__popc(grp));
        }
        __syncthreads();
        if (tid == 0) {
            int cum = 0, chosen = 0, kk = k;
            for (int bin = 255; bin >= 0; --bin) {
                int c = (int)hist[bin];
                if (cum + c >= kk) { chosen = bin; kk -= cum; break; }
                cum += c;
            }
            sh_chosen = chosen; sh_k = kk;
        }
        __syncthreads();
        prefix |= ((unsigned)sh_chosen << shift);
        pmask  |= (0xFFu << shift);
        k = sh_k;
        __syncthreads();
    }
    unsigned T = prefix;        // 300th value's ordered bits
    int need = k;               // taken from the ==T tier (lowest indices)

    if (tid == 0) { sh_cnt = 0; sh_running = 0; }
    for (int i = tid; i < 512; i += bdim) keys[i] = 0ull;
    __syncthreads();

    // strictly-greater elements (count = 300 - need); order fixed by sort
    for (int i = tid; i < NCAND; i += bdim) {
        unsigned u = ordf(ms[i]);
        if (u > T) {
            int p = atomicAdd(&sh_cnt, 1);
            if (p < 512)
                keys[p] = ((unsigned long long)u << 32) |
                          (unsigned long long)(0xFFFFFFFFu - (unsigned)i);
        }
    }
    __syncthreads();
    int cntGt = sh_cnt;

    // ==T ties in ascending global index order (exact top_k tie semantics)
    int wrp = tid >> 5;
    for (int base = 0; base < NCAND; base += bdim) {
        int i = base + tid;
        int flag = (i < NCAND) && (ordf(ms[i]) == T);
        unsigned bal = __ballot_sync(0xFFFFFFFFu, flag);
        if (lane == 0) wsum[wrp] = __popc(bal);
        __syncthreads();
        if (tid == 0) {
            int acc = 0;
            for (int w2 = 0; w2 < 32; ++w2) { woff[w2] = acc; acc += wsum[w2]; }
            woff[32] = acc;
        }
        __syncthreads();
        if (flag) {
            int rank = __popc(bal & ((1u << lane) - 1u));
            int pos = sh_running + woff[wrp] + rank;
            int dst = cntGt + pos;
            if (pos < need && dst < 512)
                keys[dst] = ((unsigned long long)T << 32) |
                            (unsigned long long)(0xFFFFFFFFu - (unsigned)i);
        }
        __syncthreads();
        if (tid == 0) sh_running += woff[32];
        __syncthreads();
    }

    // bitonic sort 512 keys, descending (zero pad sorts last)
    for (int kk = 2; kk <= 512; kk <<= 1) {
        for (int j = kk >> 1; j > 0; j >>= 1) {
            if (tid < 512) {
                int ixj = tid ^ j;
                if (ixj > tid) {
                    unsigned long long va = keys[tid], vc = keys[ixj];
                    bool desc = ((tid & kk) == 0);
                    if (desc ? (va < vc) : (va > vc)) { keys[tid] = vc; keys[ixj] = va; }
                }
            }
            __syncthreads();
        }
    }

    for (int j = tid; j < MAXDET; j += bdim) {
        unsigned long long key = keys[j];
        int idx = (int)(0xFFFFFFFFu - (unsigned)(key & 0xFFFFFFFFull));
        if (idx < 0 || idx >= NCAND) idx = 0;
        g_selidx [b * MAXDET + j] = idx;
        g_selmask[b * MAXDET + j] = ms[idx];
    }
}

// ======== K3: fused box decode + parallel-bitmask NMS (block per batch) ====
__global__ __launch_bounds__(1024) void k_boxnms(const float* __restrict__ x,
                                                 const float* __restrict__ anchors,
                                                 float* __restrict__ out) {
    __shared__ float4   bx[MAXDET];
    __shared__ unsigned sup[MAXDET * NWORDS];
    __shared__ unsigned keepw_s[NWORDS];
    int b = blockIdx.x, tid = threadIdx.x;

    // ---- Phase A: decode selected boxes; write boxes/scores/labels ----
    if (tid < MAXDET) {
        int t = b * MAXDET + tid;
        int idx = g_selidx[t];
        float m = g_selmask[t];
        int a = idx % AA;
        int s = idx / AA;
        int hh = s / WW, ww = s % WW;

        const float* p = x + ((size_t)b * (AA * 85) + (size_t)a * 85) * SPAT + s;
        float t0 = __ldg(p), t1 = __ldg(p + SPAT);
        float t2 = __ldg(p + 2 * SPAT), t3 = __ldg(p + 3 * SPAT);

        float sx = __fsub_rn(__fmul_rn(1.2f, xla_sigmoid(t0)), 0.1f);
        float sy = __fsub_rn(__fmul_rn(1.2f, xla_sigmoid(t1)), 0.1f);
        float bxc = __fdiv_rn(__fadd_rn(sx, (float)ww), (float)WW);
        float byc = __fdiv_rn(__fadd_rn(sy, (float)hh), (float)HH);
        float bw = fminf(fmaxf(__fmul_rn(expf(t2), __ldg(anchors + a * 2 + 0)), 0.0f), 2.0f);
        float bh = fminf(fmaxf(__fmul_rn(expf(t3), __ldg(anchors + a * 2 + 1)), 0.0f), 2.0f);
        float x1 = __fsub_rn(bxc, __fmul_rn(0.5f, bw));
        float y1 = __fsub_rn(byc, __fmul_rn(0.5f, bh));
        float x2 = __fadd_rn(x1, bw);
        float y2 = __fadd_rn(y1, bh);
        x1 = fminf(fmaxf(x1, 0.0f), 1.0f);
        y1 = fminf(fmaxf(y1, 0.0f), 1.0f);
        x2 = fminf(fmaxf(x2, 0.0f), 1.0f);
        y2 = fminf(fmaxf(y2, 0.0f), 1.0f);

        bx[tid] = make_float4(x1, y1, x2, y2);
        float* ob = out + (size_t)t * 4;
        ob[0] = x1; ob[1] = y1; ob[2] = x2; ob[3] = y2;
        out[(size_t)BATCH * MAXDET * 4 + t] = (m >= 0.0f) ? m : 0.0f;
        out[(size_t)BATCH * MAXDET * 5 + t] = (float)g_label[(size_t)b * NCAND + idx];
    }
    __syncthreads();

    // ---- Phase B: suppression bit matrix (iou > 0.7, j > i) in parallel ----
    for (int task = tid; task < MAXDET * NWORDS; task += blockDim.x) {
        int i = task / NWORDS, w = task % NWORDS;
        float4 bi = bx[i];
        float ai = __fmul_rn(__fsub_rn(bi.z, bi.x), __fsub_rn(bi.w, bi.y));
        unsigned bits = 0;
        int j0 = w * 32;
        #pragma unroll 8
        for (int jj = 0; jj < 32; ++jj) {
            int j = j0 + jj;
            if (j > i && j < MAXDET) {
                float4 bj = bx[j];
                float lx = fmaxf(bi.x, bj.x), ly = fmaxf(bi.y, bj.y);
                float rx = fminf(bi.z, bj.z), ry = fminf(bi.w, bj.w);
                float iw = fmaxf(__fsub_rn(rx, lx), 0.0f);
                float ih = fmaxf(__fsub_rn(ry, ly), 0.0f);
                float inter = __fmul_rn(iw, ih);
                float aj = __fmul_rn(__fsub_rn(bj.z, bj.x), __fsub_rn(bj.w, bj.y));
                float den = __fadd_rn(__fsub_rn(__fadd_rn(ai, aj), inter), 1e-9f);
                float iou = __fdiv_rn(inter, den);
                if (iou > 0.7f) bits |= (1u << jj);
            }
        }
        sup[task] = bits;
    }
    __syncthreads();

    // ---- Phase C: sequential greedy scan on one warp (bit ops only) ----
    if (tid < 32) {
        int l = tid;
        unsigned kw = 0;
        if (l < NWORDS) {
            for (int jj = 0; jj < 32; ++jj) {
                int j = l * 32 + jj;
                if (j < MAXDET && g_selmask[b * MAXDET + j] >= 0.0f) kw |= (1u << jj);
            }
        }
        for (int i = 0; i < MAXDET; ++i) {
            unsigned wrd = __shfl_sync(0xFFFFFFFFu, kw, i >> 5);
            if ((wrd >> (i & 31)) & 1u) {            // warp-uniform branch
                if (l < NWORDS) kw &= ~sup[i * NWORDS + l];
            }
        }
        if (l < NWORDS) keepw_s[l] = kw;
    }
    __syncthreads();
    for (int j = tid; j < MAXDET; j += blockDim.x)
        out[(size_t)BATCH * MAXDET * 6 + b * MAXDET + j] =
            ((keepw_s[j >> 5] >> (j & 31)) & 1u) ? 1.0f : 0.0f;
}

// ================= launch =================
extern "C" void kernel_launch(void* const* d_in, const int* in_sizes, int n_in,
                              void* d_out, int out_size) {
    (void)out_size;
    const float* x       = (const float*)d_in[0];
    const float* anchors = (const float*)d_in[1];
    if (n_in >= 2) {
        if (in_sizes[1] == X_ELEMS || in_sizes[0] < in_sizes[1]) {
            x = (const float*)d_in[1]; anchors = (const float*)d_in[0];
        }
    }
    float* out = (float*)d_out;

    dim3 g1((SPAT + 127) / 128, AA, BATCH);
    k_decode<<<g1, 128>>>(x);
    k_select<<<BATCH, 1024>>>();
    k_boxnms<<<BATCH, 1024>>>(x, anchors, out);
}